// round 2
// baseline (speedup 1.0000x reference)
#include <cuda_runtime.h>
#include <mma.h>
#include <cstdint>

using namespace nvcuda;

#define BB 256      // batch
#define SS 256      // encoder seq len
#define DD 64       // input dim
#define HH 1024     // hidden
#define G4 4096     // 4*H
#define TOUT 32     // decode steps

// ---------------- static device scratch (no allocs allowed) ----------------
__device__ float g_W0enc[(size_t)G4 * 1088];   // [Whh0 | Wih0] tf32-rounded
__device__ float g_W1enc[(size_t)G4 * 2048];   // [Whh1 | Wih1]
__device__ float g_W0dec[(size_t)G4 * 1024];   // dec Whh0
__device__ float g_W1dec[(size_t)G4 * 2048];   // [dec Whh1 | dec Wih1]
__device__ float g_h0[2][BB * HH];
__device__ float g_h1[2][BB * HH];
__device__ float g_c0[BB * HH];
__device__ float g_c1[BB * HH];
__device__ float g_pred[BB];

__device__ __forceinline__ float to_tf32(float x) {
    float r;
    asm("cvt.rna.tf32.f32 %0, %1;" : "=f"(r) : "f"(x));
    return r;
}

__device__ __forceinline__ float sigmoidf_(float x) {
    return 1.0f / (1.0f + expf(-x));
}

// ---------------- setup: concat + tf32-round weights, zero states ----------
__global__ void setup_kernel(const float* __restrict__ eWih0, const float* __restrict__ eWhh0,
                             const float* __restrict__ eWih1, const float* __restrict__ eWhh1,
                             const float* __restrict__ dWhh0,
                             const float* __restrict__ dWih1, const float* __restrict__ dWhh1)
{
    const size_t s0 = (size_t)G4 * 1088;
    const size_t s1 = (size_t)G4 * 2048;
    const size_t s2 = (size_t)G4 * 2048;
    const size_t s3 = (size_t)G4 * 1024;
    const size_t s4 = (size_t)4 * BB * HH;   // zero: h0[0], h1[0], c0, c1
    const size_t s5 = BB;                    // zero: pred
    const size_t total = s0 + s1 + s2 + s3 + s4 + s5;

    for (size_t i = (size_t)blockIdx.x * blockDim.x + threadIdx.x; i < total;
         i += (size_t)gridDim.x * blockDim.x) {
        size_t x = i;
        if (x < s0) {
            size_t r = x / 1088, k = x % 1088;
            float v = (k < 1024) ? eWhh0[r * 1024 + k] : eWih0[r * 64 + (k - 1024)];
            g_W0enc[x] = to_tf32(v);
            continue;
        }
        x -= s0;
        if (x < s1) {
            size_t r = x / 2048, k = x % 2048;
            float v = (k < 1024) ? eWhh1[r * 1024 + k] : eWih1[r * 1024 + (k - 1024)];
            g_W1enc[x] = to_tf32(v);
            continue;
        }
        x -= s1;
        if (x < s2) {
            size_t r = x / 2048, k = x % 2048;
            float v = (k < 1024) ? dWhh1[r * 1024 + k] : dWih1[r * 1024 + (k - 1024)];
            g_W1dec[x] = to_tf32(v);
            continue;
        }
        x -= s2;
        if (x < s3) {
            g_W0dec[x] = to_tf32(dWhh0[x]);
            continue;
        }
        x -= s3;
        if (x < s4) {
            size_t seg = x / ((size_t)BB * HH);
            size_t off = x % ((size_t)BB * HH);
            if (seg == 0) g_h0[0][off] = 0.0f;
            else if (seg == 1) g_h1[0][off] = 0.0f;
            else if (seg == 2) g_c0[off] = 0.0f;
            else g_c1[off] = 0.0f;
            continue;
        }
        x -= s4;
        g_pred[x] = 0.0f;
    }
}

// ---------------- fused LSTM cell: GEMM(tf32 wmma) + gates + c/h -----------
// grid: (32 j-tiles, 4 row-tiles), 256 threads (8 warps = 2 M x 4 gates)
// Each CTA computes gates for rows [row0,row0+64) and hidden cols [j0,j0+32)
// for all four gates simultaneously, then does the cell update in-epilogue.
enum { AUX_NONE = 0, AUX_X = 1, AUX_H = 2 };

__global__ void __launch_bounds__(256)
lstm_cell(const float* __restrict__ Xptr,       // X base (AUX_X only)
          const float* __restrict__ bias,       // [4096]
          const float* __restrict__ sw,         // scalar-input weights [4096] or null
          int K, int t, int auxmode, int layer, int par, int wsel)
{
    __shared__ float smem[64 * 128];            // 32 KB; staged A/W, then C
    float* As = smem;                           // [64][32]
    float* Ws = smem + 64 * 32;                 // [128][32] (4 gates x 32 j) x 32 k

    const float* hprev = layer ? g_h1[par] : g_h0[par];
    float*       hout  = layer ? g_h1[par ^ 1] : g_h0[par ^ 1];
    float*       c_io  = layer ? g_c1 : g_c0;
    const float* aux   = (auxmode == AUX_X) ? Xptr : g_h0[par ^ 1];
    const float* W =
        (wsel == 0) ? g_W0enc : (wsel == 1) ? g_W1enc : (wsel == 2) ? g_W0dec : g_W1dec;

    const int tid  = threadIdx.x;
    const int warp = tid >> 5;
    const int wm   = warp & 1;    // M sub-tile (0..1)
    const int wg   = warp >> 1;   // gate (0..3)
    const int row0 = blockIdx.y * 64;
    const int j0   = blockIdx.x * 32;

    wmma::fragment<wmma::accumulator, 16, 16, 8, float> acc[2][2];
#pragma unroll
    for (int i = 0; i < 2; i++)
#pragma unroll
        for (int j = 0; j < 2; j++) wmma::fill_fragment(acc[i][j], 0.0f);

    const int nch = K >> 5;
    for (int ck = 0; ck < nch; ck++) {
        const int kk = ck << 5;
        // stage A tile 64x32 (tf32-round on the fly)
#pragma unroll
        for (int it = 0; it < 2; it++) {
            int idx = tid + it * 256;           // 0..511
            int r = idx >> 3, c4 = (idx & 7) << 2;
            int b = row0 + r;
            int kg = kk + c4;
            float4 v;
            if (auxmode == AUX_NONE || kg < 1024) {
                v = *(const float4*)(hprev + (size_t)b * HH + kg);
            } else if (auxmode == AUX_X) {
                v = *(const float4*)(aux + (size_t)b * (SS * DD) + t * DD + (kg - 1024));
            } else {
                v = *(const float4*)(aux + (size_t)b * HH + (kg - 1024));
            }
            v.x = to_tf32(v.x); v.y = to_tf32(v.y);
            v.z = to_tf32(v.z); v.w = to_tf32(v.w);
            *(float4*)(As + r * 32 + c4) = v;
        }
        // stage W tile 128x32 (already tf32)
#pragma unroll
        for (int it = 0; it < 4; it++) {
            int idx = tid + it * 256;           // 0..1023
            int n = idx >> 3, c4 = (idx & 7) << 2;
            int g = n >> 5, jj = n & 31;
            size_t r = (size_t)g * 1024 + j0 + jj;
            *(float4*)(Ws + n * 32 + c4) = *(const float4*)(W + r * (size_t)K + kk + c4);
        }
        __syncthreads();

#pragma unroll
        for (int k8 = 0; k8 < 4; k8++) {
            wmma::fragment<wmma::matrix_a, 16, 16, 8, wmma::precision::tf32, wmma::row_major> af[2];
            wmma::fragment<wmma::matrix_b, 16, 16, 8, wmma::precision::tf32, wmma::col_major> bf[2];
#pragma unroll
            for (int i = 0; i < 2; i++)
                wmma::load_matrix_sync(af[i], As + (wm * 32 + i * 16) * 32 + k8 * 8, 32);
#pragma unroll
            for (int j = 0; j < 2; j++)
                wmma::load_matrix_sync(bf[j], Ws + (wg * 32 + j * 16) * 32 + k8 * 8, 32);
#pragma unroll
            for (int i = 0; i < 2; i++)
#pragma unroll
                for (int j = 0; j < 2; j++)
                    wmma::mma_sync(acc[i][j], af[i], bf[j], acc[i][j]);
        }
        __syncthreads();
    }

    // dump accumulators to smem C [64 rows][128 = gate*32 + jj]
#pragma unroll
    for (int i = 0; i < 2; i++)
#pragma unroll
        for (int j = 0; j < 2; j++)
            wmma::store_matrix_sync(smem + (wm * 32 + i * 16) * 128 + (wg * 32 + j * 16),
                                    acc[i][j], 128, wmma::mem_row_major);
    __syncthreads();

    // epilogue: LSTM cell update, 8 (b,j) elements per thread
#pragma unroll
    for (int e = 0; e < 8; e++) {
        int idx = tid + e * 256;                // 0..2047
        int r = idx >> 5;                       // 0..63
        int jj = idx & 31;
        int b = row0 + r;
        int j = j0 + jj;

        float gi = smem[r * 128 + 0 * 32 + jj] + bias[j];
        float gf = smem[r * 128 + 1 * 32 + jj] + bias[1024 + j];
        float gg = smem[r * 128 + 2 * 32 + jj] + bias[2048 + j];
        float go = smem[r * 128 + 3 * 32 + jj] + bias[3072 + j];

        if (sw) {  // decoder layer 0: scalar input contribution
            float p = g_pred[b];
            gi += p * sw[j];
            gf += p * sw[1024 + j];
            gg += p * sw[2048 + j];
            go += p * sw[3072 + j];
        }

        size_t o = (size_t)b * HH + j;
        float c  = c_io[o];
        float cn = sigmoidf_(gf) * c + sigmoidf_(gi) * tanhf(gg);
        float hn = sigmoidf_(go) * tanhf(cn);
        c_io[o] = cn;
        hout[o] = hn;
    }
}

// ---------------- fc: pred[b] = dot(h1[b], fcW) + fcb ----------------------
__global__ void fc_kernel(const float* __restrict__ fcW, const float* __restrict__ fcb,
                          float* __restrict__ out, int par, int t)
{
    int gw = (blockIdx.x * blockDim.x + threadIdx.x) >> 5;   // global warp = batch row
    int lane = threadIdx.x & 31;
    if (gw >= BB) return;
    const float* hr = g_h1[par] + (size_t)gw * HH;
    float s = 0.0f;
#pragma unroll 8
    for (int k = lane; k < HH; k += 32) s += hr[k] * fcW[k];
#pragma unroll
    for (int o = 16; o; o >>= 1) s += __shfl_xor_sync(0xFFFFFFFFu, s, o);
    if (lane == 0) {
        float p = s + fcb[0];
        out[(size_t)gw * TOUT + t] = p;
        g_pred[gw] = p;
    }
}

// ---------------- launch ----------------------------------------------------
extern "C" void kernel_launch(void* const* d_in, const int* in_sizes, int n_in,
                              void* d_out, int out_size)
{
    const float* X       = (const float*)d_in[0];
    const float* eWih0   = (const float*)d_in[1];
    const float* eWhh0   = (const float*)d_in[2];
    const float* eb0     = (const float*)d_in[3];
    const float* eWih1   = (const float*)d_in[4];
    const float* eWhh1   = (const float*)d_in[5];
    const float* eb1     = (const float*)d_in[6];
    const float* dWih0   = (const float*)d_in[7];
    const float* dWhh0   = (const float*)d_in[8];
    const float* db0     = (const float*)d_in[9];
    const float* dWih1   = (const float*)d_in[10];
    const float* dWhh1   = (const float*)d_in[11];
    const float* db1     = (const float*)d_in[12];
    const float* fcW     = (const float*)d_in[13];
    const float* fcb     = (const float*)d_in[14];
    float* out           = (float*)d_out;

    setup_kernel<<<1024, 256>>>(eWih0, eWhh0, eWih1, eWhh1, dWhh0, dWih1, dWhh1);

    dim3 grid(32, 4);
    int par = 0;

    // encoder: 256 steps, layers interleaved
    for (int t = 0; t < SS; t++) {
        lstm_cell<<<grid, 256>>>(X, eb0, nullptr, 1088, t, AUX_X, 0, par, 0);
        lstm_cell<<<grid, 256>>>(nullptr, eb1, nullptr, 2048, t, AUX_H, 1, par, 1);
        par ^= 1;
    }

    // decoder: 32 autoregressive steps
    for (int t = 0; t < TOUT; t++) {
        lstm_cell<<<grid, 256>>>(nullptr, db0, dWih0, 1024, t, AUX_NONE, 0, par, 2);
        lstm_cell<<<grid, 256>>>(nullptr, db1, nullptr, 2048, t, AUX_H, 1, par, 3);
        fc_kernel<<<8, 1024>>>(fcW, fcb, out, par ^ 1, t);
        par ^= 1;
    }
}

// round 4
// speedup vs baseline: 1.8559x; 1.8559x over previous
#include <cuda_runtime.h>
#include <mma.h>
#include <cstdint>

using namespace nvcuda;

#define BB 256      // batch
#define SS 256      // encoder seq len
#define DD 64       // input dim
#define HH 1024     // hidden
#define G4 4096     // 4*H
#define TOUT 32     // decode steps
#define APAD 36     // smem tile row stride (floats), 16B-aligned padding

// ---------------- static device scratch ----------------
__device__ float g_W0enc[(size_t)G4 * 1088];   // [Whh0 | Wih0] tf32-rounded
__device__ float g_W1enc[(size_t)G4 * 2048];   // [Whh1 | Wih1]
__device__ float g_W0dec[(size_t)G4 * 1024];   // dec Whh0
__device__ float g_W1dec[(size_t)G4 * 2048];   // [dec Whh1 | dec Wih1]
__device__ float g_X[(size_t)BB * SS * DD];    // tf32-rounded X
__device__ float g_h0[2][BB * HH];
__device__ float g_h1[2][BB * HH];
__device__ float g_c0[BB * HH];
__device__ float g_c1[BB * HH];
__device__ float g_pred[BB];

__device__ __forceinline__ float to_tf32(float x) {
    float r;
    asm("cvt.rna.tf32.f32 %0, %1;" : "=f"(r) : "f"(x));
    return r;
}
__device__ __forceinline__ float sigmoidf_(float x) { return 1.0f / (1.0f + expf(-x)); }

__device__ __forceinline__ void cpa16(void* s, const void* g) {
    unsigned sa = (unsigned)__cvta_generic_to_shared(s);
    asm volatile("cp.async.ca.shared.global [%0], [%1], 16;\n" ::"r"(sa), "l"(g));
}
__device__ __forceinline__ void cpa_commit() { asm volatile("cp.async.commit_group;\n"); }
__device__ __forceinline__ void cpa_wait1() { asm volatile("cp.async.wait_group 1;\n"); }
__device__ __forceinline__ void cpa_wait0() { asm volatile("cp.async.wait_group 0;\n"); }

// ---------------- setup ----------------
__global__ void setup_kernel(const float* __restrict__ X,
                             const float* __restrict__ eWih0, const float* __restrict__ eWhh0,
                             const float* __restrict__ eWih1, const float* __restrict__ eWhh1,
                             const float* __restrict__ dWhh0,
                             const float* __restrict__ dWih1, const float* __restrict__ dWhh1)
{
    const size_t s0 = (size_t)G4 * 1088;
    const size_t s1 = (size_t)G4 * 2048;
    const size_t s2 = (size_t)G4 * 2048;
    const size_t s3 = (size_t)G4 * 1024;
    const size_t sx = (size_t)BB * SS * DD;
    const size_t s4 = (size_t)4 * BB * HH;
    const size_t s5 = BB;
    const size_t total = s0 + s1 + s2 + s3 + sx + s4 + s5;

    for (size_t i = (size_t)blockIdx.x * blockDim.x + threadIdx.x; i < total;
         i += (size_t)gridDim.x * blockDim.x) {
        size_t x = i;
        if (x < s0) {
            size_t r = x / 1088, k = x % 1088;
            float v = (k < 1024) ? eWhh0[r * 1024 + k] : eWih0[r * 64 + (k - 1024)];
            g_W0enc[x] = to_tf32(v);
            continue;
        }
        x -= s0;
        if (x < s1) {
            size_t r = x / 2048, k = x % 2048;
            float v = (k < 1024) ? eWhh1[r * 1024 + k] : eWih1[r * 1024 + (k - 1024)];
            g_W1enc[x] = to_tf32(v);
            continue;
        }
        x -= s1;
        if (x < s2) {
            size_t r = x / 2048, k = x % 2048;
            float v = (k < 1024) ? dWhh1[r * 1024 + k] : dWih1[r * 1024 + (k - 1024)];
            g_W1dec[x] = to_tf32(v);
            continue;
        }
        x -= s2;
        if (x < s3) { g_W0dec[x] = to_tf32(dWhh0[x]); continue; }
        x -= s3;
        if (x < sx) { g_X[x] = to_tf32(X[x]); continue; }
        x -= sx;
        if (x < s4) {
            size_t seg = x / ((size_t)BB * HH);
            size_t off = x % ((size_t)BB * HH);
            if (seg == 0) g_h0[0][off] = 0.0f;
            else if (seg == 1) g_h1[0][off] = 0.0f;
            else if (seg == 2) g_c0[off] = 0.0f;
            else g_c1[off] = 0.0f;
            continue;
        }
        x -= s4;
        g_pred[x] = 0.0f;
    }
}

// ---------------- fused LSTM cell GEMM ----------------
// One "role" = one layer-step. CTA computes full batch (M=256) x 64 gate-cols
// (4 gates x 16 hidden cols, j-tile = blockIdx-derived). cp.async double-buffered.
// 8 warps = 4(m) x 2(n), warp tile 64x32.
//
// smem (dynamic, floats):
//   As[2][256][APAD]  @ 0          (18432 floats)
//   Bs[2][ 64][APAD]  @ 18432      ( 4608 floats)
//   Cs[256][64] aliases As after mainloop
#define ASZ (256 * APAD)
#define BSZ (64 * APAD)
#define SMEM_FLOATS (2 * ASZ + 2 * BSZ)

struct Role {
    const float* W;        // weight, row-major [4096, K]
    const float* Ah;       // h part of A (row stride HH)
    const float* aux;      // second A part base (or null)
    size_t aux_stride;     // row stride of aux
    float* hout;
    float* c_io;
    const float* bias;     // [4096]
    const float* sw;       // scalar-input weights [4096] or null
    int K;
};

__device__ __forceinline__ void cell_body(const Role& R, int jt, float* smem, int tid)
{
    float* As[2] = { smem, smem + ASZ };
    float* Bs[2] = { smem + 2 * ASZ, smem + 2 * ASZ + BSZ };
    const int j0 = jt * 16;
    const int warp = tid >> 5;
    const int wm = warp & 3;       // 0..3  (m)
    const int wn = warp >> 2;      // 0..1  (n)
    const int nch = R.K >> 5;

    // --- chunk loader ---
    auto load_chunk = [&](int ck, int buf) {
        const int kk = ck << 5;
        float* a = As[buf];
#pragma unroll
        for (int it = 0; it < 8; it++) {
            int u = tid + it * 256;          // 0..2047
            int r = u >> 3, c4 = (u & 7) << 2;
            int kg = kk + c4;
            const float* src = (kg < 1024)
                ? R.Ah + (size_t)r * HH + kg
                : R.aux + (size_t)r * R.aux_stride + (kg - 1024);
            cpa16(a + r * APAD + c4, src);
        }
        float* b = Bs[buf];
#pragma unroll
        for (int it = 0; it < 2; it++) {
            int u = tid + it * 256;          // 0..511
            int n = u >> 3, c4 = (u & 7) << 2;
            int g = n >> 4, jj = n & 15;
            const float* src = R.W + (size_t)(g * 1024 + j0 + jj) * R.K + kk + c4;
            cpa16(b + n * APAD + c4, src);
        }
        cpa_commit();
    };

    wmma::fragment<wmma::accumulator, 16, 16, 8, float> acc[4][2];
#pragma unroll
    for (int i = 0; i < 4; i++)
#pragma unroll
        for (int j = 0; j < 2; j++) wmma::fill_fragment(acc[i][j], 0.0f);

    load_chunk(0, 0);

    for (int ck = 0; ck < nch; ck++) {
        const int buf = ck & 1;
        if (ck + 1 < nch) { load_chunk(ck + 1, buf ^ 1); cpa_wait1(); }
        else              { cpa_wait0(); }
        __syncthreads();

        const float* a = As[buf];
        const float* b = Bs[buf];
#pragma unroll
        for (int k8 = 0; k8 < 4; k8++) {
            wmma::fragment<wmma::matrix_a, 16, 16, 8, wmma::precision::tf32, wmma::row_major> af[4];
            wmma::fragment<wmma::matrix_b, 16, 16, 8, wmma::precision::tf32, wmma::col_major> bf[2];
#pragma unroll
            for (int i = 0; i < 4; i++)
                wmma::load_matrix_sync(af[i], a + (wm * 64 + i * 16) * APAD + k8 * 8, APAD);
#pragma unroll
            for (int j = 0; j < 2; j++)
                wmma::load_matrix_sync(bf[j], b + (wn * 32 + j * 16) * APAD + k8 * 8, APAD);
#pragma unroll
            for (int i = 0; i < 4; i++)
#pragma unroll
                for (int j = 0; j < 2; j++)
                    wmma::mma_sync(acc[i][j], af[i], bf[j], acc[i][j]);
        }
        __syncthreads();
    }

    // --- epilogue: dump C, cell update ---
    float* Cs = smem;   // [256][64]
#pragma unroll
    for (int i = 0; i < 4; i++)
#pragma unroll
        for (int j = 0; j < 2; j++)
            wmma::store_matrix_sync(Cs + (wm * 64 + i * 16) * 64 + (wn * 32 + j * 16),
                                    acc[i][j], 64, wmma::mem_row_major);
    __syncthreads();

#pragma unroll
    for (int e = 0; e < 16; e++) {
        int idx = tid + e * 256;     // 0..4095 = 256 rows x 16 j
        int r = idx >> 4;
        int jj = idx & 15;
        int b = r;
        int j = j0 + jj;

        float gi = Cs[r * 64 + 0 * 16 + jj] + R.bias[j];
        float gf = Cs[r * 64 + 1 * 16 + jj] + R.bias[1024 + j];
        float gg = Cs[r * 64 + 2 * 16 + jj] + R.bias[2048 + j];
        float go = Cs[r * 64 + 3 * 16 + jj] + R.bias[3072 + j];

        if (R.sw) {
            float p = g_pred[b];
            gi += p * R.sw[j];
            gf += p * R.sw[1024 + j];
            gg += p * R.sw[2048 + j];
            go += p * R.sw[3072 + j];
        }

        size_t o = (size_t)b * HH + j;
        float c  = R.c_io[o];
        float cn = sigmoidf_(gf) * c + sigmoidf_(gi) * tanhf(gg);
        float hn = sigmoidf_(go) * tanhf(cn);
        R.c_io[o] = cn;
        R.hout[o] = to_tf32(hn);   // pre-round: next step's GEMM input
    }
}

// mode: 0 = encoder fused [L1(t) | L0(t+1)], 1 = enc L0(t), 2 = enc L1(t),
//       3 = dec L0(t), 4 = dec L1(t)
__global__ void __launch_bounds__(256, 1)
cell_kernel(const float* __restrict__ bias0, const float* __restrict__ bias1,
            const float* __restrict__ sw0, int t, int par, int mode)
{
    extern __shared__ float smem[];
    const int tid = threadIdx.x;

    int roleL1, jt;
    if (mode == 0) { roleL1 = (blockIdx.x < 64); jt = blockIdx.x & 63; }
    else           { roleL1 = (mode == 2 || mode == 4); jt = blockIdx.x; }

    Role R;
    if (mode <= 2) {
        if (roleL1) {  // encoder layer 1, step t
            R.W = g_W1enc; R.K = 2048;
            R.Ah = g_h1[par]; R.aux = g_h0[par ^ 1]; R.aux_stride = HH;
            R.hout = g_h1[par ^ 1]; R.c_io = g_c1;
            R.bias = bias1; R.sw = nullptr;
        } else {       // encoder layer 0, step s
            int s, parS;
            if (mode == 0) { s = t + 1; parS = par ^ 1; }
            else           { s = t;     parS = par;     }
            R.W = g_W0enc; R.K = 1088;
            R.Ah = g_h0[parS]; R.aux = g_X + (size_t)s * DD; R.aux_stride = (size_t)SS * DD;
            R.hout = g_h0[parS ^ 1]; R.c_io = g_c0;
            R.bias = bias0; R.sw = nullptr;
        }
    } else if (mode == 3) {   // decoder layer 0
        R.W = g_W0dec; R.K = 1024;
        R.Ah = g_h0[par]; R.aux = g_h0[par]; R.aux_stride = HH;  // aux unused (K=1024)
        R.hout = g_h0[par ^ 1]; R.c_io = g_c0;
        R.bias = bias0; R.sw = sw0;
    } else {                  // decoder layer 1
        R.W = g_W1dec; R.K = 2048;
        R.Ah = g_h1[par]; R.aux = g_h0[par ^ 1]; R.aux_stride = HH;
        R.hout = g_h1[par ^ 1]; R.c_io = g_c1;
        R.bias = bias1; R.sw = nullptr;
    }

    cell_body(R, jt, smem, tid);
}

// ---------------- fc: pred[b] = dot(h1[b], fcW) + fcb ----------------------
__global__ void fc_kernel(const float* __restrict__ fcW, const float* __restrict__ fcb,
                          float* __restrict__ out, int par, int t)
{
    int gw = (blockIdx.x * blockDim.x + threadIdx.x) >> 5;
    int lane = threadIdx.x & 31;
    if (gw >= BB) return;
    const float* hr = g_h1[par] + (size_t)gw * HH;
    float s = 0.0f;
#pragma unroll 8
    for (int k = lane; k < HH; k += 32) s += hr[k] * fcW[k];
#pragma unroll
    for (int o = 16; o; o >>= 1) s += __shfl_xor_sync(0xFFFFFFFFu, s, o);
    if (lane == 0) {
        float p = s + fcb[0];
        out[(size_t)gw * TOUT + t] = p;
        g_pred[gw] = p;
    }
}

// ---------------- launch ----------------------------------------------------
extern "C" void kernel_launch(void* const* d_in, const int* in_sizes, int n_in,
                              void* d_out, int out_size)
{
    const float* X     = (const float*)d_in[0];
    const float* eWih0 = (const float*)d_in[1];
    const float* eWhh0 = (const float*)d_in[2];
    const float* eb0   = (const float*)d_in[3];
    const float* eWih1 = (const float*)d_in[4];
    const float* eWhh1 = (const float*)d_in[5];
    const float* eb1   = (const float*)d_in[6];
    const float* dWih0 = (const float*)d_in[7];
    const float* dWhh0 = (const float*)d_in[8];
    const float* db0   = (const float*)d_in[9];
    const float* dWih1 = (const float*)d_in[10];
    const float* dWhh1 = (const float*)d_in[11];
    const float* db1   = (const float*)d_in[12];
    const float* fcW   = (const float*)d_in[13];
    const float* fcb   = (const float*)d_in[14];
    float* out         = (float*)d_out;

    const size_t smem_bytes = SMEM_FLOATS * sizeof(float);
    cudaFuncSetAttribute(cell_kernel, cudaFuncAttributeMaxDynamicSharedMemorySize,
                         (int)smem_bytes);

    setup_kernel<<<1024, 256>>>(X, eWih0, eWhh0, eWih1, eWhh1, dWhh0, dWih1, dWhh1);

    // encoder: software-pipelined wavefront (L1(t) runs with L0(t+1) in one launch)
    cell_kernel<<<64, 256, smem_bytes>>>(eb0, nullptr, nullptr, 0, 0, 1);      // L0(0)
    for (int t = 0; t < SS - 1; t++)
        cell_kernel<<<128, 256, smem_bytes>>>(eb0, eb1, nullptr, t, t & 1, 0); // L1(t)+L0(t+1)
    cell_kernel<<<64, 256, smem_bytes>>>(nullptr, eb1, nullptr, SS - 1, (SS - 1) & 1, 2);

    // after encoder: h0 final in g_h0[0], h1 final in g_h1[0]
    int par = 0;
    for (int t = 0; t < TOUT; t++) {
        cell_kernel<<<64, 256, smem_bytes>>>(db0, nullptr, dWih0, t, par, 3);
        cell_kernel<<<64, 256, smem_bytes>>>(nullptr, db1, nullptr, t, par, 4);
        fc_kernel<<<8, 1024>>>(fcW, fcb, out, par ^ 1, t);
        par ^= 1;
    }
}

// round 8
// speedup vs baseline: 1.8830x; 1.0146x over previous
#include <cuda_runtime.h>
#include <mma.h>
#include <cstdint>

using namespace nvcuda;

#define BB 256      // batch
#define SS 256      // encoder seq len
#define DD 64       // input dim
#define HH 1024     // hidden
#define G4 4096     // 4*H
#define TOUT 32     // decode steps
#define APAD 36     // smem tile row stride (floats), 16B-aligned padding

// ---------------- static device scratch ----------------
__device__ float g_W0enc[(size_t)G4 * 1088];   // [Whh0 | Wih0] tf32-rounded
__device__ float g_W1enc[(size_t)G4 * 2048];   // [Whh1 | Wih1]
__device__ float g_W0dec[(size_t)G4 * 1024];   // dec Whh0
__device__ float g_W1dec[(size_t)G4 * 2048];   // [dec Whh1 | dec Wih1]
__device__ float g_X[(size_t)BB * SS * DD];    // tf32-rounded X
__device__ float g_h0[2][BB * HH];
__device__ float g_h1[2][BB * HH];
__device__ float g_c0[BB * HH];
__device__ float g_c1[BB * HH];
__device__ float g_pred[BB];

__device__ __forceinline__ float to_tf32(float x) {
    float r;
    asm("cvt.rna.tf32.f32 %0, %1;" : "=f"(r) : "f"(x));
    return r;
}
__device__ __forceinline__ float sigmoidf_(float x) { return 1.0f / (1.0f + expf(-x)); }

__device__ __forceinline__ void cpa16(void* s, const void* g) {
    unsigned sa = (unsigned)__cvta_generic_to_shared(s);
    asm volatile("cp.async.ca.shared.global [%0], [%1], 16;\n" ::"r"(sa), "l"(g));
}
__device__ __forceinline__ void cpa_commit() { asm volatile("cp.async.commit_group;\n"); }
__device__ __forceinline__ void cpa_wait2() { asm volatile("cp.async.wait_group 2;\n"); }
__device__ __forceinline__ void cpa_wait1() { asm volatile("cp.async.wait_group 1;\n"); }
__device__ __forceinline__ void cpa_wait0() { asm volatile("cp.async.wait_group 0;\n"); }

// ---------------- setup ----------------
__global__ void setup_kernel(const float* __restrict__ X,
                             const float* __restrict__ eWih0, const float* __restrict__ eWhh0,
                             const float* __restrict__ eWih1, const float* __restrict__ eWhh1,
                             const float* __restrict__ dWhh0,
                             const float* __restrict__ dWih1, const float* __restrict__ dWhh1)
{
    const size_t s0 = (size_t)G4 * 1088;
    const size_t s1 = (size_t)G4 * 2048;
    const size_t s2 = (size_t)G4 * 2048;
    const size_t s3 = (size_t)G4 * 1024;
    const size_t sx = (size_t)BB * SS * DD;
    const size_t s4 = (size_t)4 * BB * HH;
    const size_t s5 = BB;
    const size_t total = s0 + s1 + s2 + s3 + sx + s4 + s5;

    for (size_t i = (size_t)blockIdx.x * blockDim.x + threadIdx.x; i < total;
         i += (size_t)gridDim.x * blockDim.x) {
        size_t x = i;
        if (x < s0) {
            size_t r = x / 1088, k = x % 1088;
            float v = (k < 1024) ? eWhh0[r * 1024 + k] : eWih0[r * 64 + (k - 1024)];
            g_W0enc[x] = to_tf32(v);
            continue;
        }
        x -= s0;
        if (x < s1) {
            size_t r = x / 2048, k = x % 2048;
            float v = (k < 1024) ? eWhh1[r * 1024 + k] : eWih1[r * 1024 + (k - 1024)];
            g_W1enc[x] = to_tf32(v);
            continue;
        }
        x -= s1;
        if (x < s2) {
            size_t r = x / 2048, k = x % 2048;
            float v = (k < 1024) ? dWhh1[r * 1024 + k] : dWih1[r * 1024 + (k - 1024)];
            g_W1dec[x] = to_tf32(v);
            continue;
        }
        x -= s2;
        if (x < s3) { g_W0dec[x] = to_tf32(dWhh0[x]); continue; }
        x -= s3;
        if (x < sx) { g_X[x] = to_tf32(X[x]); continue; }
        x -= sx;
        if (x < s4) {
            size_t seg = x / ((size_t)BB * HH);
            size_t off = x % ((size_t)BB * HH);
            if (seg == 0) g_h0[0][off] = 0.0f;
            else if (seg == 1) g_h1[0][off] = 0.0f;
            else if (seg == 2) g_c0[off] = 0.0f;
            else g_c1[off] = 0.0f;
            continue;
        }
        x -= s4;
        g_pred[x] = 0.0f;
    }
}

// ---------------- fused LSTM cell GEMM (4-stage cp.async, 1 sync/chunk) ----
// CTA: full batch (M=256) x 64 gate-cols (4 gates x 16 j). 8 warps = 4m x 2n,
// warp tile 64x32.
#define NSTG 4
#define ASZ (256 * APAD)
#define BSZ (64 * APAD)
#define STG (ASZ + BSZ)
#define SMEM_FLOATS (NSTG * STG)

struct Role {
    const float* W;        // weight, row-major [4096, K]
    const float* Ah;       // h part of A (row stride HH)
    const float* aux;      // second A part base (or null)
    size_t aux_stride;     // row stride of aux
    float* hout;
    float* c_io;
    const float* bias;     // [4096]
    const float* sw;       // scalar-input weights [4096] or null
    int K;
};

__device__ __forceinline__ void cell_body(const Role& R, int jt, float* smem, int tid)
{
    const int j0 = jt * 16;
    const int warp = tid >> 5;
    const int wm = warp & 3;       // 0..3  (m)
    const int wn = warp >> 2;      // 0..1  (n)
    const int nch = R.K >> 5;

    auto load_chunk = [&](int ck) {
        float* a = smem + (ck & (NSTG - 1)) * STG;
        float* b = a + ASZ;
        const int kk = ck << 5;
#pragma unroll
        for (int it = 0; it < 8; it++) {
            int u = tid + it * 256;          // 0..2047
            int r = u >> 3, c4 = (u & 7) << 2;
            int kg = kk + c4;
            const float* src = (kg < 1024)
                ? R.Ah + (size_t)r * HH + kg
                : R.aux + (size_t)r * R.aux_stride + (kg - 1024);
            cpa16(a + r * APAD + c4, src);
        }
#pragma unroll
        for (int it = 0; it < 2; it++) {
            int u = tid + it * 256;          // 0..511
            int n = u >> 3, c4 = (u & 7) << 2;
            int g = n >> 4, jj = n & 15;
            const float* src = R.W + (size_t)(g * 1024 + j0 + jj) * R.K + kk + c4;
            cpa16(b + n * APAD + c4, src);
        }
        cpa_commit();
    };

    wmma::fragment<wmma::accumulator, 16, 16, 8, float> acc[4][2];
#pragma unroll
    for (int i = 0; i < 4; i++)
#pragma unroll
        for (int j = 0; j < 2; j++) wmma::fill_fragment(acc[i][j], 0.0f);

    // preload first NSTG-1 chunks
    load_chunk(0);
    load_chunk(1);
    load_chunk(2);

    for (int ck = 0; ck < nch; ck++) {
        // wait until chunk ck has landed (tail: fewer groups remain in flight)
        if (ck == nch - 1)      cpa_wait0();
        else if (ck == nch - 2) cpa_wait1();
        else                    cpa_wait2();
        __syncthreads();   // all warps done computing ck-1; chunk ck visible

        if (ck + NSTG - 1 < nch) load_chunk(ck + NSTG - 1);  // into slot (ck-1)&3

        const float* a = smem + (ck & (NSTG - 1)) * STG;
        const float* b = a + ASZ;
#pragma unroll
        for (int k8 = 0; k8 < 4; k8++) {
            wmma::fragment<wmma::matrix_a, 16, 16, 8, wmma::precision::tf32, wmma::row_major> af[4];
            wmma::fragment<wmma::matrix_b, 16, 16, 8, wmma::precision::tf32, wmma::col_major> bf[2];
#pragma unroll
            for (int i = 0; i < 4; i++)
                wmma::load_matrix_sync(af[i], a + (wm * 64 + i * 16) * APAD + k8 * 8, APAD);
#pragma unroll
            for (int j = 0; j < 2; j++)
                wmma::load_matrix_sync(bf[j], b + (wn * 32 + j * 16) * APAD + k8 * 8, APAD);
#pragma unroll
            for (int i = 0; i < 4; i++)
#pragma unroll
                for (int j = 0; j < 2; j++)
                    wmma::mma_sync(acc[i][j], af[i], bf[j], acc[i][j]);
        }
    }
    __syncthreads();   // all compute done before C overwrites stage smem

    // --- epilogue: dump C, cell update ---
    float* Cs = smem;   // [256][64]
#pragma unroll
    for (int i = 0; i < 4; i++)
#pragma unroll
        for (int j = 0; j < 2; j++)
            wmma::store_matrix_sync(Cs + (wm * 64 + i * 16) * 64 + (wn * 32 + j * 16),
                                    acc[i][j], 64, wmma::mem_row_major);
    __syncthreads();

#pragma unroll
    for (int e = 0; e < 16; e++) {
        int idx = tid + e * 256;     // 0..4095 = 256 rows x 16 j
        int r = idx >> 4;
        int jj = idx & 15;
        int b = r;
        int j = j0 + jj;

        float gi = Cs[r * 64 + 0 * 16 + jj] + R.bias[j];
        float gf = Cs[r * 64 + 1 * 16 + jj] + R.bias[1024 + j];
        float gg = Cs[r * 64 + 2 * 16 + jj] + R.bias[2048 + j];
        float go = Cs[r * 64 + 3 * 16 + jj] + R.bias[3072 + j];

        if (R.sw) {
            float p = g_pred[b];
            gi += p * R.sw[j];
            gf += p * R.sw[1024 + j];
            gg += p * R.sw[2048 + j];
            go += p * R.sw[3072 + j];
        }

        size_t o = (size_t)b * HH + j;
        float c  = R.c_io[o];
        float cn = sigmoidf_(gf) * c + sigmoidf_(gi) * tanhf(gg);
        float hn = sigmoidf_(go) * tanhf(cn);
        R.c_io[o] = cn;
        R.hout[o] = to_tf32(hn);   // pre-round: next step's GEMM input
    }
}

// mode: 0 = encoder fused [L1(t) | L0(t+1)], 1 = enc L0(t), 2 = enc L1(t),
//       3 = dec L0(t), 4 = dec L1(t)
__global__ void __launch_bounds__(256, 1)
cell_kernel(const float* __restrict__ bias0, const float* __restrict__ bias1,
            const float* __restrict__ sw0, int t, int par, int mode)
{
    extern __shared__ float smem[];
    const int tid = threadIdx.x;

    int roleL1, jt;
    if (mode == 0) { roleL1 = (blockIdx.x < 64); jt = blockIdx.x & 63; }
    else           { roleL1 = (mode == 2 || mode == 4); jt = blockIdx.x; }

    Role R;
    if (mode <= 2) {
        if (roleL1) {  // encoder layer 1, step t
            R.W = g_W1enc; R.K = 2048;
            R.Ah = g_h1[par]; R.aux = g_h0[par ^ 1]; R.aux_stride = HH;
            R.hout = g_h1[par ^ 1]; R.c_io = g_c1;
            R.bias = bias1; R.sw = nullptr;
        } else {       // encoder layer 0, step s
            int s, parS;
            if (mode == 0) { s = t + 1; parS = par ^ 1; }
            else           { s = t;     parS = par;     }
            R.W = g_W0enc; R.K = 1088;
            R.Ah = g_h0[parS]; R.aux = g_X + (size_t)s * DD; R.aux_stride = (size_t)SS * DD;
            R.hout = g_h0[parS ^ 1]; R.c_io = g_c0;
            R.bias = bias0; R.sw = nullptr;
        }
    } else if (mode == 3) {   // decoder layer 0
        R.W = g_W0dec; R.K = 1024;
        R.Ah = g_h0[par]; R.aux = g_h0[par]; R.aux_stride = HH;  // aux unused (K=1024)
        R.hout = g_h0[par ^ 1]; R.c_io = g_c0;
        R.bias = bias0; R.sw = sw0;
    } else {                  // decoder layer 1
        R.W = g_W1dec; R.K = 2048;
        R.Ah = g_h1[par]; R.aux = g_h0[par ^ 1]; R.aux_stride = HH;
        R.hout = g_h1[par ^ 1]; R.c_io = g_c1;
        R.bias = bias1; R.sw = nullptr;
    }

    cell_body(R, jt, smem, tid);
}

// ---------------- fc: pred[b] = dot(h1[b], fcW) + fcb ----------------------
__global__ void fc_kernel(const float* __restrict__ fcW, const float* __restrict__ fcb,
                          float* __restrict__ out, int par, int t)
{
    int gw = (blockIdx.x * blockDim.x + threadIdx.x) >> 5;
    int lane = threadIdx.x & 31;
    if (gw >= BB) return;
    const float* hr = g_h1[par] + (size_t)gw * HH;
    float s = 0.0f;
#pragma unroll 8
    for (int k = lane; k < HH; k += 32) s += hr[k] * fcW[k];
#pragma unroll
    for (int o = 16; o; o >>= 1) s += __shfl_xor_sync(0xFFFFFFFFu, s, o);
    if (lane == 0) {
        float p = s + fcb[0];
        out[(size_t)gw * TOUT + t] = p;
        g_pred[gw] = p;
    }
}

// ---------------- launch ----------------------------------------------------
extern "C" void kernel_launch(void* const* d_in, const int* in_sizes, int n_in,
                              void* d_out, int out_size)
{
    const float* X     = (const float*)d_in[0];
    const float* eWih0 = (const float*)d_in[1];
    const float* eWhh0 = (const float*)d_in[2];
    const float* eb0   = (const float*)d_in[3];
    const float* eWih1 = (const float*)d_in[4];
    const float* eWhh1 = (const float*)d_in[5];
    const float* eb1   = (const float*)d_in[6];
    const float* dWih0 = (const float*)d_in[7];
    const float* dWhh0 = (const float*)d_in[8];
    const float* db0   = (const float*)d_in[9];
    const float* dWih1 = (const float*)d_in[10];
    const float* dWhh1 = (const float*)d_in[11];
    const float* db1   = (const float*)d_in[12];
    const float* fcW   = (const float*)d_in[13];
    const float* fcb   = (const float*)d_in[14];
    float* out         = (float*)d_out;

    const size_t smem_bytes = SMEM_FLOATS * sizeof(float);   // 184320 B
    cudaFuncSetAttribute(cell_kernel, cudaFuncAttributeMaxDynamicSharedMemorySize,
                         (int)smem_bytes);

    setup_kernel<<<1024, 256>>>(X, eWih0, eWhh0, eWih1, eWhh1, dWhh0, dWih1, dWhh1);

    // encoder: software-pipelined wavefront (L1(t) runs with L0(t+1) in one launch)
    cell_kernel<<<64, 256, smem_bytes>>>(eb0, nullptr, nullptr, 0, 0, 1);      // L0(0)
    for (int t = 0; t < SS - 1; t++)
        cell_kernel<<<128, 256, smem_bytes>>>(eb0, eb1, nullptr, t, t & 1, 0); // L1(t)+L0(t+1)
    cell_kernel<<<64, 256, smem_bytes>>>(nullptr, eb1, nullptr, SS - 1, (SS - 1) & 1, 2);

    // decoder (final enc states in g_h0[0], g_h1[0])
    int par = 0;
    for (int t = 0; t < TOUT; t++) {
        cell_kernel<<<64, 256, smem_bytes>>>(db0, nullptr, dWih0, t, par, 3);
        cell_kernel<<<64, 256, smem_bytes>>>(nullptr, db1, nullptr, t, par, 4);
        fc_kernel<<<8, 1024>>>(fcW, fcb, out, par ^ 1, t);
        par ^= 1;
    }
}

// round 9
// speedup vs baseline: 2.4773x; 1.3156x over previous
#include <cuda_runtime.h>
#include <mma.h>
#include <cstdint>

using namespace nvcuda;

#define BB 256      // batch
#define SS 256      // encoder seq len
#define DD 64       // input dim
#define HH 1024     // hidden
#define G4 4096     // 4*H
#define TOUT 32     // decode steps
#define APAD 36     // smem tile row stride (floats)

// ---------------- static device scratch ----------------
__device__ float g_W0enc[(size_t)G4 * 1088];   // [Whh0 | Wih0] tf32-rounded
__device__ float g_W1enc[(size_t)G4 * 2048];   // [Whh1 | Wih1]
__device__ float g_W0dec[(size_t)G4 * 1024];   // dec Whh0
__device__ float g_W1dec[(size_t)G4 * 2048];   // [dec Whh1 | dec Wih1]
__device__ float g_X[(size_t)BB * SS * DD];    // tf32-rounded X
__device__ float g_h0[2][BB * HH];
__device__ float g_h1[2][BB * HH];
__device__ float g_c0[BB * HH];
__device__ float g_c1[BB * HH];
__device__ float g_pred[BB];

__device__ __forceinline__ float to_tf32(float x) {
    float r;
    asm("cvt.rna.tf32.f32 %0, %1;" : "=f"(r) : "f"(x));
    return r;
}
__device__ __forceinline__ float sigmoidf_(float x) { return 1.0f / (1.0f + expf(-x)); }

__device__ __forceinline__ void cpa16(void* s, const void* g) {
    unsigned sa = (unsigned)__cvta_generic_to_shared(s);
    asm volatile("cp.async.ca.shared.global [%0], [%1], 16;\n" ::"r"(sa), "l"(g));
}
__device__ __forceinline__ void cpa_commit() { asm volatile("cp.async.commit_group;\n"); }
__device__ __forceinline__ void cpa_wait2() { asm volatile("cp.async.wait_group 2;\n"); }
__device__ __forceinline__ void cpa_wait1() { asm volatile("cp.async.wait_group 1;\n"); }
__device__ __forceinline__ void cpa_wait0() { asm volatile("cp.async.wait_group 0;\n"); }

// ---------------- setup ----------------
__global__ void setup_kernel(const float* __restrict__ X,
                             const float* __restrict__ eWih0, const float* __restrict__ eWhh0,
                             const float* __restrict__ eWih1, const float* __restrict__ eWhh1,
                             const float* __restrict__ dWhh0,
                             const float* __restrict__ dWih1, const float* __restrict__ dWhh1)
{
    const size_t s0 = (size_t)G4 * 1088;
    const size_t s1 = (size_t)G4 * 2048;
    const size_t s2 = (size_t)G4 * 2048;
    const size_t s3 = (size_t)G4 * 1024;
    const size_t sx = (size_t)BB * SS * DD;
    const size_t s4 = (size_t)4 * BB * HH;
    const size_t s5 = BB;
    const size_t total = s0 + s1 + s2 + s3 + sx + s4 + s5;

    for (size_t i = (size_t)blockIdx.x * blockDim.x + threadIdx.x; i < total;
         i += (size_t)gridDim.x * blockDim.x) {
        size_t x = i;
        if (x < s0) {
            size_t r = x / 1088, k = x % 1088;
            float v = (k < 1024) ? eWhh0[r * 1024 + k] : eWih0[r * 64 + (k - 1024)];
            g_W0enc[x] = to_tf32(v);
            continue;
        }
        x -= s0;
        if (x < s1) {
            size_t r = x / 2048, k = x % 2048;
            float v = (k < 1024) ? eWhh1[r * 1024 + k] : eWih1[r * 1024 + (k - 1024)];
            g_W1enc[x] = to_tf32(v);
            continue;
        }
        x -= s1;
        if (x < s2) {
            size_t r = x / 2048, k = x % 2048;
            float v = (k < 1024) ? dWhh1[r * 1024 + k] : dWih1[r * 1024 + (k - 1024)];
            g_W1dec[x] = to_tf32(v);
            continue;
        }
        x -= s2;
        if (x < s3) { g_W0dec[x] = to_tf32(dWhh0[x]); continue; }
        x -= s3;
        if (x < sx) { g_X[x] = to_tf32(X[x]); continue; }
        x -= sx;
        if (x < s4) {
            size_t seg = x / ((size_t)BB * HH);
            size_t off = x % ((size_t)BB * HH);
            if (seg == 0) g_h0[0][off] = 0.0f;
            else if (seg == 1) g_h1[0][off] = 0.0f;
            else if (seg == 2) g_c0[off] = 0.0f;
            else g_c1[off] = 0.0f;
            continue;
        }
        x -= s4;
        g_pred[x] = 0.0f;
    }
}

// ---------------- fused LSTM cell GEMM ----------------
// CTA tile: M=128 batch rows x N=64 gate-cols (4 gates x 16 j). 8 warps = 4m x 2n,
// warp tile 32x32. 4-stage cp.async ring, 1 syncthreads per chunk.
// 2 CTAs/SM (launch_bounds) -> 16 warps/SM = 4 per SMSP.
#define NSTG 4
#define MT 128                       // CTA M tile
#define ASZ (MT * APAD)
#define BSZ (64 * APAD)
#define STG (ASZ + BSZ)
#define SMEM_FLOATS (NSTG * STG)     // 27648 floats = 110592 B

struct Role {
    const float* W;        // weight, row-major [4096, K]
    const float* Ah;       // h part of A (row stride HH)
    const float* aux;      // second A part base (or null)
    size_t aux_stride;     // row stride of aux
    float* hout;
    float* c_io;
    const float* bias;     // [4096]
    const float* sw;       // scalar-input weights [4096] or null
    int K;
};

__device__ __forceinline__ void cell_body(const Role& R, int mt, int jt, float* smem, int tid)
{
    const int j0 = jt * 16;
    const int m0 = mt * MT;
    const int warp = tid >> 5;
    const int wm = warp & 3;       // 0..3  (m, 32 rows each)
    const int wn = warp >> 2;      // 0..1  (n, 32 cols each)
    const int nch = R.K >> 5;

    auto load_chunk = [&](int ck) {
        float* a = smem + (ck & (NSTG - 1)) * STG;
        float* b = a + ASZ;
        const int kk = ck << 5;
#pragma unroll
        for (int it = 0; it < 4; it++) {
            int u = tid + it * 256;          // 0..1023
            int r = u >> 3, c4 = (u & 7) << 2;
            int kg = kk + c4;
            const float* src = (kg < 1024)
                ? R.Ah + (size_t)(m0 + r) * HH + kg
                : R.aux + (size_t)(m0 + r) * R.aux_stride + (kg - 1024);
            cpa16(a + r * APAD + c4, src);
        }
#pragma unroll
        for (int it = 0; it < 2; it++) {
            int u = tid + it * 256;          // 0..511
            int n = u >> 3, c4 = (u & 7) << 2;
            int g = n >> 4, jj = n & 15;
            const float* src = R.W + (size_t)(g * 1024 + j0 + jj) * R.K + kk + c4;
            cpa16(b + n * APAD + c4, src);
        }
        cpa_commit();
    };

    wmma::fragment<wmma::accumulator, 16, 16, 8, float> acc[2][2];
#pragma unroll
    for (int i = 0; i < 2; i++)
#pragma unroll
        for (int j = 0; j < 2; j++) wmma::fill_fragment(acc[i][j], 0.0f);

    load_chunk(0);
    load_chunk(1);
    load_chunk(2);

    for (int ck = 0; ck < nch; ck++) {
        if (ck == nch - 1)      cpa_wait0();
        else if (ck == nch - 2) cpa_wait1();
        else                    cpa_wait2();
        __syncthreads();

        if (ck + NSTG - 1 < nch) load_chunk(ck + NSTG - 1);

        const float* a = smem + (ck & (NSTG - 1)) * STG;
        const float* b = a + ASZ;
#pragma unroll
        for (int k8 = 0; k8 < 4; k8++) {
            wmma::fragment<wmma::matrix_a, 16, 16, 8, wmma::precision::tf32, wmma::row_major> af[2];
            wmma::fragment<wmma::matrix_b, 16, 16, 8, wmma::precision::tf32, wmma::col_major> bf[2];
#pragma unroll
            for (int i = 0; i < 2; i++)
                wmma::load_matrix_sync(af[i], a + (wm * 32 + i * 16) * APAD + k8 * 8, APAD);
#pragma unroll
            for (int j = 0; j < 2; j++)
                wmma::load_matrix_sync(bf[j], b + (wn * 32 + j * 16) * APAD + k8 * 8, APAD);
#pragma unroll
            for (int i = 0; i < 2; i++)
#pragma unroll
                for (int j = 0; j < 2; j++)
                    wmma::mma_sync(acc[i][j], af[i], bf[j], acc[i][j]);
        }
    }
    __syncthreads();   // compute done before C overwrites stage smem

    // --- epilogue: dump C [128][64], cell update ---
    float* Cs = smem;
#pragma unroll
    for (int i = 0; i < 2; i++)
#pragma unroll
        for (int j = 0; j < 2; j++)
            wmma::store_matrix_sync(Cs + (wm * 32 + i * 16) * 64 + (wn * 32 + j * 16),
                                    acc[i][j], 64, wmma::mem_row_major);
    __syncthreads();

#pragma unroll
    for (int e = 0; e < 8; e++) {
        int idx = tid + e * 256;     // 0..2047 = 128 rows x 16 j
        int r = idx >> 4;
        int jj = idx & 15;
        int b = m0 + r;
        int j = j0 + jj;

        float gi = Cs[r * 64 + 0 * 16 + jj] + R.bias[j];
        float gf = Cs[r * 64 + 1 * 16 + jj] + R.bias[1024 + j];
        float gg = Cs[r * 64 + 2 * 16 + jj] + R.bias[2048 + j];
        float go = Cs[r * 64 + 3 * 16 + jj] + R.bias[3072 + j];

        if (R.sw) {
            float p = g_pred[b];
            gi += p * R.sw[j];
            gf += p * R.sw[1024 + j];
            gg += p * R.sw[2048 + j];
            go += p * R.sw[3072 + j];
        }

        size_t o = (size_t)b * HH + j;
        float c  = R.c_io[o];
        float cn = sigmoidf_(gf) * c + sigmoidf_(gi) * tanhf(gg);
        float hn = sigmoidf_(go) * tanhf(cn);
        R.c_io[o] = cn;
        R.hout[o] = to_tf32(hn);   // pre-round: next step's GEMM input
    }
}

// mode: 0 = encoder fused [L1(t) | L0(t+1)], 1 = enc L0(t), 2 = enc L1(t),
//       3 = dec L0(t), 4 = dec L1(t)
// per-role CTA count = 128 (64 j-tiles x 2 m-tiles); fused = 256.
__global__ void __launch_bounds__(256, 2)
cell_kernel(const float* __restrict__ bias0, const float* __restrict__ bias1,
            const float* __restrict__ sw0, int t, int par, int mode)
{
    extern __shared__ float smem[];
    const int tid = threadIdx.x;

    int roleL1, local;
    if (mode == 0) { roleL1 = (blockIdx.x < 128); local = blockIdx.x & 127; }
    else           { roleL1 = (mode == 2 || mode == 4); local = blockIdx.x; }
    const int mt = local & 1;
    const int jt = local >> 1;

    Role R;
    if (mode <= 2) {
        if (roleL1) {  // encoder layer 1, step t
            R.W = g_W1enc; R.K = 2048;
            R.Ah = g_h1[par]; R.aux = g_h0[par ^ 1]; R.aux_stride = HH;
            R.hout = g_h1[par ^ 1]; R.c_io = g_c1;
            R.bias = bias1; R.sw = nullptr;
        } else {       // encoder layer 0, step s
            int s, parS;
            if (mode == 0) { s = t + 1; parS = par ^ 1; }
            else           { s = t;     parS = par;     }
            R.W = g_W0enc; R.K = 1088;
            R.Ah = g_h0[parS]; R.aux = g_X + (size_t)s * DD; R.aux_stride = (size_t)SS * DD;
            R.hout = g_h0[parS ^ 1]; R.c_io = g_c0;
            R.bias = bias0; R.sw = nullptr;
        }
    } else if (mode == 3) {   // decoder layer 0
        R.W = g_W0dec; R.K = 1024;
        R.Ah = g_h0[par]; R.aux = g_h0[par]; R.aux_stride = HH;  // aux unused (K=1024)
        R.hout = g_h0[par ^ 1]; R.c_io = g_c0;
        R.bias = bias0; R.sw = sw0;
    } else {                  // decoder layer 1
        R.W = g_W1dec; R.K = 2048;
        R.Ah = g_h1[par]; R.aux = g_h0[par ^ 1]; R.aux_stride = HH;
        R.hout = g_h1[par ^ 1]; R.c_io = g_c1;
        R.bias = bias1; R.sw = nullptr;
    }

    cell_body(R, mt, jt, smem, tid);
}

// ---------------- fc: pred[b] = dot(h1[b], fcW) + fcb ----------------------
__global__ void fc_kernel(const float* __restrict__ fcW, const float* __restrict__ fcb,
                          float* __restrict__ out, int par, int t)
{
    int gw = (blockIdx.x * blockDim.x + threadIdx.x) >> 5;
    int lane = threadIdx.x & 31;
    if (gw >= BB) return;
    const float* hr = g_h1[par] + (size_t)gw * HH;
    float s = 0.0f;
#pragma unroll 8
    for (int k = lane; k < HH; k += 32) s += hr[k] * fcW[k];
#pragma unroll
    for (int o = 16; o; o >>= 1) s += __shfl_xor_sync(0xFFFFFFFFu, s, o);
    if (lane == 0) {
        float p = s + fcb[0];
        out[(size_t)gw * TOUT + t] = p;
        g_pred[gw] = p;
    }
}

// ---------------- launch ----------------------------------------------------
extern "C" void kernel_launch(void* const* d_in, const int* in_sizes, int n_in,
                              void* d_out, int out_size)
{
    const float* X     = (const float*)d_in[0];
    const float* eWih0 = (const float*)d_in[1];
    const float* eWhh0 = (const float*)d_in[2];
    const float* eb0   = (const float*)d_in[3];
    const float* eWih1 = (const float*)d_in[4];
    const float* eWhh1 = (const float*)d_in[5];
    const float* eb1   = (const float*)d_in[6];
    const float* dWih0 = (const float*)d_in[7];
    const float* dWhh0 = (const float*)d_in[8];
    const float* db0   = (const float*)d_in[9];
    const float* dWih1 = (const float*)d_in[10];
    const float* dWhh1 = (const float*)d_in[11];
    const float* db1   = (const float*)d_in[12];
    const float* fcW   = (const float*)d_in[13];
    const float* fcb   = (const float*)d_in[14];
    float* out         = (float*)d_out;

    const size_t smem_bytes = SMEM_FLOATS * sizeof(float);   // 110592 B
    cudaFuncSetAttribute(cell_kernel, cudaFuncAttributeMaxDynamicSharedMemorySize,
                         (int)smem_bytes);

    setup_kernel<<<1024, 256>>>(X, eWih0, eWhh0, eWih1, eWhh1, dWhh0, dWih1, dWhh1);

    // encoder: software-pipelined wavefront (L1(t) runs with L0(t+1) in one launch)
    cell_kernel<<<128, 256, smem_bytes>>>(eb0, nullptr, nullptr, 0, 0, 1);      // L0(0)
    for (int t = 0; t < SS - 1; t++)
        cell_kernel<<<256, 256, smem_bytes>>>(eb0, eb1, nullptr, t, t & 1, 0);  // L1(t)+L0(t+1)
    cell_kernel<<<128, 256, smem_bytes>>>(nullptr, eb1, nullptr, SS - 1, (SS - 1) & 1, 2);

    // decoder (final enc states in g_h0[0], g_h1[0])
    int par = 0;
    for (int t = 0; t < TOUT; t++) {
        cell_kernel<<<128, 256, smem_bytes>>>(db0, nullptr, dWih0, t, par, 3);
        cell_kernel<<<128, 256, smem_bytes>>>(nullptr, db1, nullptr, t, par, 4);
        fc_kernel<<<8, 1024>>>(fcW, fcb, out, par ^ 1, t);
        par ^= 1;
    }
}

// round 10
// speedup vs baseline: 8.5440x; 3.4489x over previous
#include <cuda_runtime.h>
#include <cuda_fp16.h>
#include <mma.h>
#include <cstdint>

using namespace nvcuda;

#define BB 256      // batch
#define SS 256      // encoder seq len
#define DD 64       // input dim
#define HH 1024     // hidden
#define G4 4096     // 4*H
#define TOUT 32     // decode steps
#define APAD 72     // smem tile row stride (halfs) = 144B

// ---------------- static device scratch (fp16 operands, fp32 state) --------
__device__ __half g_W0enc[(size_t)G4 * 1088];   // [Whh0 | Wih0]
__device__ __half g_W1enc[(size_t)G4 * 2048];   // [Whh1 | Wih1]
__device__ __half g_W0dec[(size_t)G4 * 1024];   // dec Whh0
__device__ __half g_W1dec[(size_t)G4 * 2048];   // [dec Whh1 | dec Wih1]
__device__ __half g_X[(size_t)BB * SS * DD];    // fp16 X
__device__ __half g_h0[2][BB * HH];
__device__ __half g_h1[2][BB * HH];
__device__ float  g_c0[BB * HH];
__device__ float  g_c1[BB * HH];
__device__ float  g_pred[BB];

__device__ __forceinline__ float sigmoidf_(float x) { return 1.0f / (1.0f + expf(-x)); }

__device__ __forceinline__ void cpa16(void* s, const void* g) {
    unsigned sa = (unsigned)__cvta_generic_to_shared(s);
    asm volatile("cp.async.ca.shared.global [%0], [%1], 16;\n" ::"r"(sa), "l"(g));
}
__device__ __forceinline__ void cpa_commit() { asm volatile("cp.async.commit_group;\n"); }
__device__ __forceinline__ void cpa_wait2() { asm volatile("cp.async.wait_group 2;\n"); }
__device__ __forceinline__ void cpa_wait1() { asm volatile("cp.async.wait_group 1;\n"); }
__device__ __forceinline__ void cpa_wait0() { asm volatile("cp.async.wait_group 0;\n"); }

// ---------------- setup: fp16 conversion, zero states ----------
__global__ void setup_kernel(const float* __restrict__ X,
                             const float* __restrict__ eWih0, const float* __restrict__ eWhh0,
                             const float* __restrict__ eWih1, const float* __restrict__ eWhh1,
                             const float* __restrict__ dWhh0,
                             const float* __restrict__ dWih1, const float* __restrict__ dWhh1)
{
    const size_t s0 = (size_t)G4 * 1088;
    const size_t s1 = (size_t)G4 * 2048;
    const size_t s2 = (size_t)G4 * 2048;
    const size_t s3 = (size_t)G4 * 1024;
    const size_t sx = (size_t)BB * SS * DD;
    const size_t s4 = (size_t)4 * BB * HH;
    const size_t s5 = BB;
    const size_t total = s0 + s1 + s2 + s3 + sx + s4 + s5;

    for (size_t i = (size_t)blockIdx.x * blockDim.x + threadIdx.x; i < total;
         i += (size_t)gridDim.x * blockDim.x) {
        size_t x = i;
        if (x < s0) {
            size_t r = x / 1088, k = x % 1088;
            float v = (k < 1024) ? eWhh0[r * 1024 + k] : eWih0[r * 64 + (k - 1024)];
            g_W0enc[x] = __float2half_rn(v);
            continue;
        }
        x -= s0;
        if (x < s1) {
            size_t r = x / 2048, k = x % 2048;
            float v = (k < 1024) ? eWhh1[r * 1024 + k] : eWih1[r * 1024 + (k - 1024)];
            g_W1enc[x] = __float2half_rn(v);
            continue;
        }
        x -= s1;
        if (x < s2) {
            size_t r = x / 2048, k = x % 2048;
            float v = (k < 1024) ? dWhh1[r * 1024 + k] : dWih1[r * 1024 + (k - 1024)];
            g_W1dec[x] = __float2half_rn(v);
            continue;
        }
        x -= s2;
        if (x < s3) { g_W0dec[x] = __float2half_rn(dWhh0[x]); continue; }
        x -= s3;
        if (x < sx) { g_X[x] = __float2half_rn(X[x]); continue; }
        x -= sx;
        if (x < s4) {
            size_t seg = x / ((size_t)BB * HH);
            size_t off = x % ((size_t)BB * HH);
            if (seg == 0) g_h0[0][off] = __float2half_rn(0.0f);
            else if (seg == 1) g_h1[0][off] = __float2half_rn(0.0f);
            else if (seg == 2) g_c0[off] = 0.0f;
            else g_c1[off] = 0.0f;
            continue;
        }
        x -= s4;
        g_pred[x] = 0.0f;
    }
}

// ---------------- fused LSTM cell GEMM (fp16 HMMA) ----------------
// CTA tile: M=128 x N=64 (4 gates x 16 j). 8 warps = 4m x 2n, warp tile 32x32.
// K-chunk = 64 halfs; 4-stage cp.async ring; 2 CTAs/SM.
#define NSTG 4
#define MT 128
#define KC 64                        // K elems per chunk
#define ASZ (MT * APAD)              // halfs
#define BSZ (64 * APAD)
#define STG (ASZ + BSZ)
#define SMEM_HALFS (NSTG * STG)      // 55296 halfs = 110592 B

struct Role {
    const __half* W;       // weight, row-major [4096, K]
    const __half* Ah;      // h part of A (row stride HH)
    const __half* aux;     // second A part base (or null)
    size_t aux_stride;     // row stride of aux
    __half* hout;
    float* c_io;
    const float* bias;     // [4096]
    const float* sw;       // scalar-input weights [4096] or null
    int K;
};

__device__ __forceinline__ void cell_body(const Role& R, int mt, int jt, __half* smem, int tid)
{
    const int j0 = jt * 16;
    const int m0 = mt * MT;
    const int warp = tid >> 5;
    const int wm = warp & 3;       // m sub-tile (32 rows)
    const int wn = warp >> 2;      // n sub-tile (32 cols)
    const int nch = R.K / KC;

    auto load_chunk = [&](int ck) {
        __half* a = smem + (ck & (NSTG - 1)) * STG;
        __half* b = a + ASZ;
        const int kk = ck * KC;
#pragma unroll
        for (int it = 0; it < 4; it++) {
            int u = tid + it * 256;          // 0..1023
            int r = u >> 3, c8 = (u & 7) << 3;
            int kg = kk + c8;
            const __half* src = (kg < 1024)
                ? R.Ah + (size_t)(m0 + r) * HH + kg
                : R.aux + (size_t)(m0 + r) * R.aux_stride + (kg - 1024);
            cpa16(a + r * APAD + c8, src);
        }
#pragma unroll
        for (int it = 0; it < 2; it++) {
            int u = tid + it * 256;          // 0..511
            int n = u >> 3, c8 = (u & 7) << 3;
            int g = n >> 4, jj = n & 15;
            const __half* src = R.W + (size_t)(g * 1024 + j0 + jj) * R.K + kk + c8;
            cpa16(b + n * APAD + c8, src);
        }
        cpa_commit();
    };

    wmma::fragment<wmma::accumulator, 16, 16, 16, float> acc[2][2];
#pragma unroll
    for (int i = 0; i < 2; i++)
#pragma unroll
        for (int j = 0; j < 2; j++) wmma::fill_fragment(acc[i][j], 0.0f);

    load_chunk(0);
    load_chunk(1);
    load_chunk(2);

    for (int ck = 0; ck < nch; ck++) {
        if (ck == nch - 1)      cpa_wait0();
        else if (ck == nch - 2) cpa_wait1();
        else                    cpa_wait2();
        __syncthreads();

        if (ck + NSTG - 1 < nch) load_chunk(ck + NSTG - 1);

        const __half* a = smem + (ck & (NSTG - 1)) * STG;
        const __half* b = a + ASZ;
#pragma unroll
        for (int k16 = 0; k16 < KC / 16; k16++) {
            wmma::fragment<wmma::matrix_a, 16, 16, 16, __half, wmma::row_major> af[2];
            wmma::fragment<wmma::matrix_b, 16, 16, 16, __half, wmma::col_major> bf[2];
#pragma unroll
            for (int i = 0; i < 2; i++)
                wmma::load_matrix_sync(af[i], a + (wm * 32 + i * 16) * APAD + k16 * 16, APAD);
#pragma unroll
            for (int j = 0; j < 2; j++)
                wmma::load_matrix_sync(bf[j], b + (wn * 32 + j * 16) * APAD + k16 * 16, APAD);
#pragma unroll
            for (int i = 0; i < 2; i++)
#pragma unroll
                for (int j = 0; j < 2; j++)
                    wmma::mma_sync(acc[i][j], af[i], bf[j], acc[i][j]);
        }
    }
    __syncthreads();   // compute done before C overwrites stage smem

    // --- epilogue: dump C [128][64] fp32, cell update ---
    float* Cs = (float*)smem;
#pragma unroll
    for (int i = 0; i < 2; i++)
#pragma unroll
        for (int j = 0; j < 2; j++)
            wmma::store_matrix_sync(Cs + (wm * 32 + i * 16) * 64 + (wn * 32 + j * 16),
                                    acc[i][j], 64, wmma::mem_row_major);
    __syncthreads();

#pragma unroll
    for (int e = 0; e < 8; e++) {
        int idx = tid + e * 256;     // 0..2047 = 128 rows x 16 j
        int r = idx >> 4;
        int jj = idx & 15;
        int b = m0 + r;
        int j = j0 + jj;

        float gi = Cs[r * 64 + 0 * 16 + jj] + R.bias[j];
        float gf = Cs[r * 64 + 1 * 16 + jj] + R.bias[1024 + j];
        float gg = Cs[r * 64 + 2 * 16 + jj] + R.bias[2048 + j];
        float go = Cs[r * 64 + 3 * 16 + jj] + R.bias[3072 + j];

        if (R.sw) {
            float p = g_pred[b];
            gi += p * R.sw[j];
            gf += p * R.sw[1024 + j];
            gg += p * R.sw[2048 + j];
            go += p * R.sw[3072 + j];
        }

        size_t o = (size_t)b * HH + j;
        float c  = R.c_io[o];
        float cn = sigmoidf_(gf) * c + sigmoidf_(gi) * tanhf(gg);
        float hn = sigmoidf_(go) * tanhf(cn);
        R.c_io[o] = cn;
        R.hout[o] = __float2half_rn(hn);
    }
}

// mode: 0 = encoder fused [L1(t) | L0(t+1)], 1 = enc L0(t), 2 = enc L1(t),
//       3 = dec L0(t), 4 = dec L1(t)
__global__ void __launch_bounds__(256, 2)
cell_kernel(const float* __restrict__ bias0, const float* __restrict__ bias1,
            const float* __restrict__ sw0, int t, int par, int mode)
{
    extern __shared__ __half smem[];
    const int tid = threadIdx.x;

    int roleL1, local;
    if (mode == 0) { roleL1 = (blockIdx.x < 128); local = blockIdx.x & 127; }
    else           { roleL1 = (mode == 2 || mode == 4); local = blockIdx.x; }
    const int mt = local & 1;
    const int jt = local >> 1;

    Role R;
    if (mode <= 2) {
        if (roleL1) {  // encoder layer 1, step t
            R.W = g_W1enc; R.K = 2048;
            R.Ah = g_h1[par]; R.aux = g_h0[par ^ 1]; R.aux_stride = HH;
            R.hout = g_h1[par ^ 1]; R.c_io = g_c1;
            R.bias = bias1; R.sw = nullptr;
        } else {       // encoder layer 0, step s
            int s, parS;
            if (mode == 0) { s = t + 1; parS = par ^ 1; }
            else           { s = t;     parS = par;     }
            R.W = g_W0enc; R.K = 1088;
            R.Ah = g_h0[parS]; R.aux = g_X + (size_t)s * DD; R.aux_stride = (size_t)SS * DD;
            R.hout = g_h0[parS ^ 1]; R.c_io = g_c0;
            R.bias = bias0; R.sw = nullptr;
        }
    } else if (mode == 3) {   // decoder layer 0
        R.W = g_W0dec; R.K = 1024;
        R.Ah = g_h0[par]; R.aux = g_h0[par]; R.aux_stride = HH;  // aux unused (K=1024)
        R.hout = g_h0[par ^ 1]; R.c_io = g_c0;
        R.bias = bias0; R.sw = sw0;
    } else {                  // decoder layer 1
        R.W = g_W1dec; R.K = 2048;
        R.Ah = g_h1[par]; R.aux = g_h0[par ^ 1]; R.aux_stride = HH;
        R.hout = g_h1[par ^ 1]; R.c_io = g_c1;
        R.bias = bias1; R.sw = nullptr;
    }

    cell_body(R, mt, jt, smem, tid);
}

// ---------------- fc: pred[b] = dot(h1[b], fcW) + fcb ----------------------
__global__ void fc_kernel(const float* __restrict__ fcW, const float* __restrict__ fcb,
                          float* __restrict__ out, int par, int t)
{
    int gw = (blockIdx.x * blockDim.x + threadIdx.x) >> 5;
    int lane = threadIdx.x & 31;
    if (gw >= BB) return;
    const __half* hr = g_h1[par] + (size_t)gw * HH;
    float s = 0.0f;
#pragma unroll 8
    for (int k = lane; k < HH; k += 32) s += __half2float(hr[k]) * fcW[k];
#pragma unroll
    for (int o = 16; o; o >>= 1) s += __shfl_xor_sync(0xFFFFFFFFu, s, o);
    if (lane == 0) {
        float p = s + fcb[0];
        out[(size_t)gw * TOUT + t] = p;
        g_pred[gw] = p;
    }
}

// ---------------- launch ----------------------------------------------------
extern "C" void kernel_launch(void* const* d_in, const int* in_sizes, int n_in,
                              void* d_out, int out_size)
{
    const float* X     = (const float*)d_in[0];
    const float* eWih0 = (const float*)d_in[1];
    const float* eWhh0 = (const float*)d_in[2];
    const float* eb0   = (const float*)d_in[3];
    const float* eWih1 = (const float*)d_in[4];
    const float* eWhh1 = (const float*)d_in[5];
    const float* eb1   = (const float*)d_in[6];
    const float* dWih0 = (const float*)d_in[7];
    const float* dWhh0 = (const float*)d_in[8];
    const float* db0   = (const float*)d_in[9];
    const float* dWih1 = (const float*)d_in[10];
    const float* dWhh1 = (const float*)d_in[11];
    const float* db1   = (const float*)d_in[12];
    const float* fcW   = (const float*)d_in[13];
    const float* fcb   = (const float*)d_in[14];
    float* out         = (float*)d_out;

    const size_t smem_bytes = SMEM_HALFS * sizeof(__half);   // 110592 B
    cudaFuncSetAttribute(cell_kernel, cudaFuncAttributeMaxDynamicSharedMemorySize,
                         (int)smem_bytes);

    setup_kernel<<<1024, 256>>>(X, eWih0, eWhh0, eWih1, eWhh1, dWhh0, dWih1, dWhh1);

    // encoder: software-pipelined wavefront (L1(t) runs with L0(t+1) in one launch)
    cell_kernel<<<128, 256, smem_bytes>>>(eb0, nullptr, nullptr, 0, 0, 1);      // L0(0)
    for (int t = 0; t < SS - 1; t++)
        cell_kernel<<<256, 256, smem_bytes>>>(eb0, eb1, nullptr, t, t & 1, 0);  // L1(t)+L0(t+1)
    cell_kernel<<<128, 256, smem_bytes>>>(nullptr, eb1, nullptr, SS - 1, (SS - 1) & 1, 2);

    // decoder (final enc states in g_h0[0], g_h1[0])
    int par = 0;
    for (int t = 0; t < TOUT; t++) {
        cell_kernel<<<128, 256, smem_bytes>>>(db0, nullptr, dWih0, t, par, 3);
        cell_kernel<<<128, 256, smem_bytes>>>(nullptr, db1, nullptr, t, par, 4);
        fc_kernel<<<8, 1024>>>(fcW, fcb, out, par ^ 1, t);
        par ^= 1;
    }
}